// round 2
// baseline (speedup 1.0000x reference)
#include <cuda_runtime.h>
#include <cuda_fp16.h>
#include <cstdint>

// ===================== problem constants =====================
#define MTOK   8192
#define KDIM   4096
#define NDIM   4096
#define BM     128
#define BN     128
#define BK     32
#define KIT    (KDIM / BK)     // 128
#define STAGE_BYTES 16384      // A 8KB + B 8KB per stage
#define SMEM_GEMM   (4 * STAGE_BYTES)

// ===================== scratch (device globals; no runtime alloc) =====================
__device__ __half g_A[(size_t)MTOK * KDIM];   // quantized activations (exact ints in fp16)
__device__ __half g_W[(size_t)NDIM * KDIM];   // weights in fp16
__device__ float  g_scale[MTOK];              // per-token scale

// ===================== helpers =====================
__device__ __forceinline__ uint32_t smem_u32(const void* p) {
    uint32_t a;
    asm("{ .reg .u64 t; cvta.to.shared.u64 t, %1; cvt.u32.u64 %0, t; }" : "=r"(a) : "l"(p));
    return a;
}

// rows of 64B (32 halfs); XOR-swizzle 16B granules so ldmatrix phases are conflict-free
#define SWZ(row, g) ((uint32_t)((row) * 64 + ((((g) ^ (((row) >> 1) & 3))) << 4)))

#define CP_ASYNC16(dst, src) \
    asm volatile("cp.async.cg.shared.global [%0], [%1], 16;" :: "r"(dst), "l"(src) : "memory")
#define CP_COMMIT() asm volatile("cp.async.commit_group;" ::: "memory")
#define CP_WAIT2()  asm volatile("cp.async.wait_group 2;" ::: "memory")

#define LDSM4(r, addr)                                                              \
    asm volatile("ldmatrix.sync.aligned.m8n8.x4.shared.b16 {%0,%1,%2,%3}, [%4];"    \
        : "=r"((r)[0]), "=r"((r)[1]), "=r"((r)[2]), "=r"((r)[3]) : "r"(addr))

#define MMA16816(d, a, b0, b1)                                                      \
    asm volatile("mma.sync.aligned.m16n8k16.row.col.f32.f16.f16.f32 "               \
        "{%0,%1,%2,%3},{%4,%5,%6,%7},{%8,%9},{%0,%1,%2,%3};"                        \
        : "+f"((d)[0]), "+f"((d)[1]), "+f"((d)[2]), "+f"((d)[3])                    \
        : "r"((a)[0]), "r"((a)[1]), "r"((a)[2]), "r"((a)[3]), "r"(b0), "r"(b1))

// ===================== kernel 1: sparsity + per-token absmax quant =====================
// one block per token; 128 threads; each thread owns 8 groups of 4 (32 elems)
__global__ void __launch_bounds__(128) prep_act_kernel(const float* __restrict__ x,
                                                       const float* __restrict__ ss) {
    __shared__ float red[4];
    const int t   = blockIdx.x;
    const int tid = threadIdx.x;
    const int lid = tid & 31, wid = tid >> 5;

    const float4* xr  = reinterpret_cast<const float4*>(x + (size_t)t * KDIM);
    const float4* ssr = reinterpret_cast<const float4*>(ss);

    float4 kept[8];
    float kmax = 0.0f;
#pragma unroll
    for (int j = 0; j < 8; ++j) {
        const int g = j * 128 + tid;            // group id 0..1023
        float4 xv = xr[g];
        float4 sv = ssr[g];
        float mm[4] = { fabsf(xv.x) * sv.x, fabsf(xv.y) * sv.y,
                        fabsf(xv.z) * sv.z, fabsf(xv.w) * sv.w };
        // two smallest, ties -> lowest index (matches jax top_k(-m, 2) stability)
        int i1 = 0;
#pragma unroll
        for (int k = 1; k < 4; ++k) if (mm[k] < mm[i1]) i1 = k;
        int i2 = -1;
#pragma unroll
        for (int k = 0; k < 4; ++k) {
            if (k == i1) continue;
            if (i2 < 0 || mm[k] < mm[i2]) i2 = k;
        }
        float v[4] = { xv.x, xv.y, xv.z, xv.w };
        v[i1] = 0.0f; v[i2] = 0.0f;
        kept[j] = make_float4(v[0], v[1], v[2], v[3]);
        kmax = fmaxf(kmax, fmaxf(fmaxf(fabsf(v[0]), fabsf(v[1])),
                                 fmaxf(fabsf(v[2]), fabsf(v[3]))));
    }
#pragma unroll
    for (int off = 16; off; off >>= 1) kmax = fmaxf(kmax, __shfl_xor_sync(~0u, kmax, off));
    if (lid == 0) red[wid] = kmax;
    __syncthreads();
    const float amax  = fmaxf(fmaxf(red[0], red[1]), fmaxf(red[2], red[3]));
    const float scale = fmaxf(amax, 1e-5f) / 127.0f;
    if (tid == 0) g_scale[t] = scale;

    uint2* dst = reinterpret_cast<uint2*>(g_A + (size_t)t * KDIM);
#pragma unroll
    for (int j = 0; j < 8; ++j) {
        const int g = j * 128 + tid;
        // IEEE division (immune to --use_fast_math); rintf = round-half-even = jnp.round
        float q0 = rintf(__fdiv_rn(kept[j].x, scale));
        float q1 = rintf(__fdiv_rn(kept[j].y, scale));
        float q2 = rintf(__fdiv_rn(kept[j].z, scale));
        float q3 = rintf(__fdiv_rn(kept[j].w, scale));
        __half2 p0 = __floats2half2_rn(q0, q1);   // exact: |q|<=127 integer
        __half2 p1 = __floats2half2_rn(q2, q3);
        uint2 pk;
        pk.x = *reinterpret_cast<uint32_t*>(&p0);
        pk.y = *reinterpret_cast<uint32_t*>(&p1);
        dst[g] = pk;
    }
}

// ===================== kernel 2: weight fp32 -> fp16 =====================
__global__ void __launch_bounds__(256) prep_w_kernel(const float* __restrict__ w) {
    const int n4 = (NDIM * KDIM) / 4;
    uint2* dst = reinterpret_cast<uint2*>(g_W);
    for (int i = blockIdx.x * blockDim.x + threadIdx.x; i < n4; i += gridDim.x * blockDim.x) {
        float4 v = reinterpret_cast<const float4*>(w)[i];
        __half2 h0 = __floats2half2_rn(v.x, v.y);
        __half2 h1 = __floats2half2_rn(v.z, v.w);
        uint2 pk;
        pk.x = *reinterpret_cast<uint32_t*>(&h0);
        pk.y = *reinterpret_cast<uint32_t*>(&h1);
        dst[i] = pk;
    }
}

// ===================== kernel 3: mma.sync fp16 GEMM =====================
// CTA 128x128x32, 8 warps (4m x 2n) each 32x64, 4-stage cp.async pipeline
__global__ void __launch_bounds__(256, 2)
gemm_kernel(const float* __restrict__ bias, float* __restrict__ out) {
    extern __shared__ char smem[];
    const uint32_t sb = smem_u32(smem);
    const int tid  = threadIdx.x, lane = tid & 31, wid = tid >> 5;
    const int m0 = blockIdx.x * BM;
    const int n0 = blockIdx.y * BN;
    const int mw = (wid & 3) * 32;      // warp m offset in CTA tile
    const int nw = (wid >> 2) * 64;     // warp n offset

    // cp.async pattern: 512 granules (16B) per tile for A and for B; 2 each per thread.
    // granule j=1 is exactly row+64 of j=0 (same g) -> one base pointer per operand.
    const int rA = tid >> 2, gAg = tid & 3;
    const uint32_t dA0 = SWZ(rA, gAg);                     // dA1 = dA0 + 64*64
    const __half* srcA0 = g_A + (size_t)(m0 + rA) * KDIM + gAg * 8;
    const __half* srcB0 = g_W + (size_t)(n0 + rA) * KDIM + gAg * 8;
    const size_t rowSkip = (size_t)64 * KDIM;

    float acc[2][8][4];
#pragma unroll
    for (int i = 0; i < 2; ++i)
#pragma unroll
        for (int j = 0; j < 8; ++j)
#pragma unroll
            for (int k = 0; k < 4; ++k) acc[i][j][k] = 0.0f;

    // prologue: fill stages 0..2
#pragma unroll
    for (int s = 0; s < 3; ++s) {
        const uint32_t a = sb + s * STAGE_BYTES;
        const uint32_t b = a + 8192;
        const int ko = s * BK;
        CP_ASYNC16(a + dA0,        srcA0 + ko);
        CP_ASYNC16(a + dA0 + 4096, srcA0 + rowSkip + ko);
        CP_ASYNC16(b + dA0,        srcB0 + ko);
        CP_ASYNC16(b + dA0 + 4096, srcB0 + rowSkip + ko);
        CP_COMMIT();
    }

    for (int it = 0; it < KIT; ++it) {
        CP_WAIT2();
        __syncthreads();

        // prefetch stage it+3 (overwrites stage it-1; everyone is past it-1 after the sync)
        if (it + 3 < KIT) {
            const uint32_t a = sb + ((it + 3) & 3) * STAGE_BYTES;
            const uint32_t b = a + 8192;
            const int ko = (it + 3) * BK;
            CP_ASYNC16(a + dA0,        srcA0 + ko);
            CP_ASYNC16(a + dA0 + 4096, srcA0 + rowSkip + ko);
            CP_ASYNC16(b + dA0,        srcB0 + ko);
            CP_ASYNC16(b + dA0 + 4096, srcB0 + rowSkip + ko);
        }
        CP_COMMIT();

        const uint32_t sA = sb + (it & 3) * STAGE_BYTES;
        const uint32_t sB = sA + 8192;

#pragma unroll
        for (int ks = 0; ks < 2; ++ks) {
            uint32_t aF[2][4], bF[4][4];
#pragma unroll
            for (int mt = 0; mt < 2; ++mt) {
                const int row = mw + mt * 16 + (lane & 15);
                const int g   = ks * 2 + (lane >> 4);
                LDSM4(aF[mt], sA + SWZ(row, g));
            }
#pragma unroll
            for (int nt = 0; nt < 4; ++nt) {
                const int row = nw + nt * 16 + (lane & 7) + ((lane >> 4) << 3);
                const int g   = ks * 2 + ((lane >> 3) & 1);
                LDSM4(bF[nt], sB + SWZ(row, g));
            }
#pragma unroll
            for (int mt = 0; mt < 2; ++mt)
#pragma unroll
                for (int nt = 0; nt < 4; ++nt) {
                    MMA16816(acc[mt][2 * nt],     aF[mt], bF[nt][0], bF[nt][1]);
                    MMA16816(acc[mt][2 * nt + 1], aF[mt], bF[nt][2], bF[nt][3]);
                }
        }
        __syncthreads();
    }

    // epilogue: scale * acc + bias, direct float2 stores
#pragma unroll
    for (int mt = 0; mt < 2; ++mt) {
        const int m = m0 + mw + mt * 16 + (lane >> 2);
        const float s0 = g_scale[m];
        const float s1 = g_scale[m + 8];
#pragma unroll
        for (int nt = 0; nt < 8; ++nt) {
            const int n = n0 + nw + nt * 8 + (lane & 3) * 2;
            const float2 b2 = *reinterpret_cast<const float2*>(bias + n);
            float2 o0, o1;
            o0.x = acc[mt][nt][0] * s0 + b2.x;
            o0.y = acc[mt][nt][1] * s0 + b2.y;
            o1.x = acc[mt][nt][2] * s1 + b2.x;
            o1.y = acc[mt][nt][3] * s1 + b2.y;
            *reinterpret_cast<float2*>(out + (size_t)m * NDIM + n)       = o0;
            *reinterpret_cast<float2*>(out + (size_t)(m + 8) * NDIM + n) = o1;
        }
    }
}

// ===================== launch =====================
extern "C" void kernel_launch(void* const* d_in, const int* in_sizes, int n_in,
                              void* d_out, int out_size) {
    const float* x    = static_cast<const float*>(d_in[0]);
    const float* w    = static_cast<const float*>(d_in[1]);
    const float* bias = static_cast<const float*>(d_in[2]);
    const float* ss   = static_cast<const float*>(d_in[3]);
    float* out = static_cast<float*>(d_out);

    prep_act_kernel<<<MTOK, 128>>>(x, ss);
    prep_w_kernel<<<4096, 256>>>(w);

    cudaFuncSetAttribute(gemm_kernel, cudaFuncAttributeMaxDynamicSharedMemorySize, SMEM_GEMM);
    dim3 grid(MTOK / BM, NDIM / BN);   // 64 x 32
    gemm_kernel<<<grid, 256, SMEM_GEMM>>>(bias, out);
}